// round 2
// baseline (speedup 1.0000x reference)
#include <cuda_runtime.h>
#include <cstdint>
#include <cmath>

// ---------------------------------------------------------------------------
// NerfactoModel fused forward:
//   hash-encode (16 levels, nearest corner, 4096-entry tables, L2-resident)
//   -> density MLP (32->64->64->16)
//   -> dir MLP (3->16->16)
//   -> color MLP (63->64->64->3, sigmoid)
// One thread = one sample. All weights staged in shared memory (broadcast
// LDS). Inner products use packed fp32x2 FMA (fma.rn.f32x2, sm_100+).
// ---------------------------------------------------------------------------

typedef unsigned long long ull;

__device__ __forceinline__ ull pk2(float a, float b) {
    ull r;
    asm("mov.b64 %0, {%1, %2};" : "=l"(r) : "f"(a), "f"(b));
    return r;
}
__device__ __forceinline__ void upk2(ull v, float& a, float& b) {
    asm("mov.b64 {%0, %1}, %2;" : "=f"(a), "=f"(b) : "l"(v));
}
// d = a*b + d, two fp32 lanes packed in 64-bit regs (exact fp32 FMA).
__device__ __forceinline__ void fma2(ull& d, ull a, ull b) {
    asm("fma.rn.f32x2 %0, %1, %2, %0;" : "+l"(d) : "l"(a), "l"(b));
}

// Accumulate acc[FOUT/2] += x[0..FIN) * W[k*FOUT + j], W row-major in smem.
template<int FIN, int FOUT>
__device__ __forceinline__ void accum_rows(ull* acc, const float* x, const float* W) {
#pragma unroll
    for (int k = 0; k < FIN; ++k) {
        ull x2 = pk2(x[k], x[k]);
        const ulonglong2* wr = reinterpret_cast<const ulonglong2*>(W + k * FOUT);
#pragma unroll
        for (int q = 0; q < FOUT / 4; ++q) {
            ulonglong2 w = wr[q];           // LDS.128, uniform address -> broadcast
            fma2(acc[2 * q + 0], x2, w.x);
            fma2(acc[2 * q + 1], x2, w.y);
        }
    }
}

template<int FOUT>
__device__ __forceinline__ void init_bias(ull* acc, const float* B) {
    const ull* bb = reinterpret_cast<const ull*>(B);
#pragma unroll
    for (int q = 0; q < FOUT / 2; ++q) acc[q] = bb[q];
}

template<int FOUT, bool RELU>
__device__ __forceinline__ void finish(const ull* acc, float* y) {
#pragma unroll
    for (int q = 0; q < FOUT / 2; ++q) {
        float a, b;
        upk2(acc[q], a, b);
        if (RELU) { a = fmaxf(a, 0.0f); b = fmaxf(b, 0.0f); }
        y[2 * q + 0] = a;
        y[2 * q + 1] = b;
    }
}

template<int FIN, int FOUT, bool RELU>
__device__ __forceinline__ void dense(const float* x, const float* W, const float* B, float* y) {
    ull acc[FOUT / 2];
    init_bias<FOUT>(acc, B);
    accum_rows<FIN, FOUT>(acc, x, W);
    finish<FOUT, RELU>(acc, y);
}

// Shared-memory layout (float offsets; all even and 16B-friendly where needed)
#define OFF_DW1 0       // 32*64 = 2048
#define OFF_DB1 2048    // 64
#define OFF_DW2 2112    // 64*64 = 4096
#define OFF_DB2 6208    // 64
#define OFF_DW3 6272    // 64*16 = 1024
#define OFF_DB3 7296    // 16
#define OFF_RW1 7312    // 3*16 = 48
#define OFF_RB1 7360    // 16
#define OFF_RW2 7376    // 16*16 = 256
#define OFF_RB2 7632    // 16
#define OFF_CW1 7648    // 63*64 = 4032
#define OFF_CB1 11680   // 64
#define OFF_CW2 11744   // 64*64 = 4096
#define OFF_CB2 15840   // 64
#define OFF_CW3 15904   // 64*3 = 192
#define OFF_CB3 16096   // 3
#define SMEM_FLOATS 16100
#define SMEM_BYTES  (SMEM_FLOATS * 4)

struct ResArr { int r[16]; };

__device__ __forceinline__ void cpy(float* dst, const float* src, int n) {
    for (int t = threadIdx.x; t < n; t += blockDim.x) dst[t] = src[t];
}

__global__ void __launch_bounds__(128, 3) nerfacto_kernel(
    const float* __restrict__ rs,      // (N,3)
    const float* __restrict__ dirs,    // (N,3)
    const int*   __restrict__ cam,     // (N,)
    const float* __restrict__ aabb,    // (2,3)
    const float* __restrict__ ht,      // (16,4096,2)
    const float* __restrict__ rw1, const float* __restrict__ rb1,
    const float* __restrict__ rw2, const float* __restrict__ rb2,
    const float* __restrict__ dw1, const float* __restrict__ db1,
    const float* __restrict__ dw2, const float* __restrict__ db2,
    const float* __restrict__ dw3, const float* __restrict__ db3,
    const float* __restrict__ cw1, const float* __restrict__ cb1,
    const float* __restrict__ cw2, const float* __restrict__ cb2,
    const float* __restrict__ cw3, const float* __restrict__ cb3,
    const float* __restrict__ app,     // (1000,32)
    float* __restrict__ out,           // (N,19)
    int n, ResArr RA)
{
    extern __shared__ float sw[];
    cpy(sw + OFF_DW1, dw1, 2048);
    cpy(sw + OFF_DB1, db1, 64);
    cpy(sw + OFF_DW2, dw2, 4096);
    cpy(sw + OFF_DB2, db2, 64);
    cpy(sw + OFF_DW3, dw3, 1024);
    cpy(sw + OFF_DB3, db3, 16);
    cpy(sw + OFF_RW1, rw1, 48);
    cpy(sw + OFF_RB1, rb1, 16);
    cpy(sw + OFF_RW2, rw2, 256);
    cpy(sw + OFF_RB2, rb2, 16);
    cpy(sw + OFF_CW1, cw1, 4032);
    cpy(sw + OFF_CB1, cb1, 64);
    cpy(sw + OFF_CW2, cw2, 4096);
    cpy(sw + OFF_CB2, cb2, 64);
    cpy(sw + OFF_CW3, cw3, 192);
    cpy(sw + OFF_CB3, cb3, 3);
    __syncthreads();

    const float a0x = __ldg(aabb + 0), a0y = __ldg(aabb + 1), a0z = __ldg(aabb + 2);
    const float a1x = __ldg(aabb + 3), a1y = __ldg(aabb + 4), a1z = __ldg(aabb + 5);
    const float dx = a1x - a0x, dy = a1y - a0y, dz = a1z - a0z;

    const float2* htp = reinterpret_cast<const float2*>(ht);

    const int stride = gridDim.x * blockDim.x;
    for (int i = blockIdx.x * blockDim.x + threadIdx.x; i < n; i += stride) {
        // ---- position normalize + clip (fp32 div matches jnp divide) ----
        float px = fminf(fmaxf((__ldg(rs + 3 * i + 0) - a0x) / dx, 0.0f), 1.0f);
        float py = fminf(fmaxf((__ldg(rs + 3 * i + 1) - a0y) / dy, 0.0f), 1.0f);
        float pz = fminf(fmaxf((__ldg(rs + 3 * i + 2) - a0z) / dz, 0.0f), 1.0f);

        // ---- independent gathers issued early (L2-resident tables) ----
        float enc[32];
#pragma unroll
        for (int l = 0; l < 16; ++l) {
            int r = RA.r[l];
            float rf = (float)(r - 1);
            int cx = (int)floorf(px * rf);
            int cy = (int)floorf(py * rf);
            int cz = (int)floorf(pz * rf);
            cx = min(max(cx, 0), r - 1);
            cy = min(max(cy, 0), r - 1);
            cz = min(max(cz, 0), r - 1);
            // PRIMES_MOD = {1, 2654435761 % 4096, 805459861 % 4096} = {1, 2481, 1941}
            unsigned h = ((unsigned)cx + (unsigned)cy * 2481u + (unsigned)cz * 1941u) & 4095u;
            float2 f = __ldg(htp + l * 4096 + h);
            enc[2 * l + 0] = f.x;
            enc[2 * l + 1] = f.y;
        }

        int ci = __ldg(cam + i);
        float av[32];
        {
            const float4* ap = reinterpret_cast<const float4*>(app + (size_t)ci * 32);
#pragma unroll
            for (int q = 0; q < 8; ++q) {
                float4 v = __ldg(ap + q);
                av[4 * q + 0] = v.x; av[4 * q + 1] = v.y;
                av[4 * q + 2] = v.z; av[4 * q + 3] = v.w;
            }
        }
        float dv[3];
        dv[0] = __ldg(dirs + 3 * i + 0);
        dv[1] = __ldg(dirs + 3 * i + 1);
        dv[2] = __ldg(dirs + 3 * i + 2);

        // ---- direction MLP: edir = relu(d@rw1+rb1)@rw2+rb2 ----
        float t16[16], edir[16];
        dense<3, 16, true>(dv, sw + OFF_RW1, sw + OFF_RB1, t16);
        dense<16, 16, false>(t16, sw + OFF_RW2, sw + OFF_RB2, edir);

        // ---- density MLP ----
        float h1[64], h2[64], dfeat[16];
        dense<32, 64, true>(enc, sw + OFF_DW1, sw + OFF_DB1, h1);
        dense<64, 64, true>(h1, sw + OFF_DW2, sw + OFF_DB2, h2);
        dense<64, 16, false>(h2, sw + OFF_DW3, sw + OFF_DB3, dfeat);

        // ---- write density + geo now (frees registers before color MLP) ----
        float* orow = out + (size_t)i * 19;
        orow[3] = fmaxf(dfeat[0], 0.0f);
#pragma unroll
        for (int j = 0; j < 15; ++j) orow[4 + j] = dfeat[1 + j];

        // ---- color MLP: cin = [geo(15), edir(16), app(32)] without a copy ----
        float c1[64], c2[64];
        {
            ull acc[32];
            init_bias<64>(acc, sw + OFF_CB1);
            accum_rows<15, 64>(acc, dfeat + 1, sw + OFF_CW1);
            accum_rows<16, 64>(acc, edir, sw + OFF_CW1 + 15 * 64);
            accum_rows<32, 64>(acc, av, sw + OFF_CW1 + 31 * 64);
            finish<64, true>(acc, c1);
        }
        dense<64, 64, true>(c1, sw + OFF_CW2, sw + OFF_CB2, c2);

        // ---- final 64->3 + sigmoid ----
#pragma unroll
        for (int j = 0; j < 3; ++j) {
            float a = sw[OFF_CB3 + j];
#pragma unroll
            for (int k = 0; k < 64; ++k)
                a = fmaf(c2[k], sw[OFF_CW3 + k * 3 + j], a);
            orow[j] = 1.0f / (1.0f + expf(-a));
        }
    }
}

extern "C" void kernel_launch(void* const* d_in, const int* in_sizes, int n_in,
                              void* d_out, int out_size) {
    const float* rs   = (const float*)d_in[0];
    const float* dirs = (const float*)d_in[1];
    const int*   cam  = (const int*)d_in[2];
    const float* aabb = (const float*)d_in[3];
    const float* ht   = (const float*)d_in[4];
    const float* rw1  = (const float*)d_in[5];
    const float* rb1  = (const float*)d_in[6];
    const float* rw2  = (const float*)d_in[7];
    const float* rb2  = (const float*)d_in[8];
    const float* dw1  = (const float*)d_in[9];
    const float* db1  = (const float*)d_in[10];
    const float* dw2  = (const float*)d_in[11];
    const float* db2  = (const float*)d_in[12];
    const float* dw3  = (const float*)d_in[13];
    const float* db3  = (const float*)d_in[14];
    const float* cw1  = (const float*)d_in[15];
    const float* cb1  = (const float*)d_in[16];
    const float* cw2  = (const float*)d_in[17];
    const float* cb2  = (const float*)d_in[18];
    const float* cw3  = (const float*)d_in[19];
    const float* cb3  = (const float*)d_in[20];
    const float* app  = (const float*)d_in[21];
    float* out = (float*)d_out;

    int n = in_sizes[0] / 3;

    // Replicate Python's RES computation bit-for-bit in double precision
    // (same libm on the same host => identical int truncation at boundaries).
    ResArr ra;
    double growth = exp((log(2048.0) - log(16.0)) / 15.0);
    for (int i = 0; i < 16; ++i)
        ra.r[i] = (int)(16.0 * pow(growth, (double)i));

    cudaFuncSetAttribute(nerfacto_kernel,
                         cudaFuncAttributeMaxDynamicSharedMemorySize, SMEM_BYTES);

    dim3 grid(456), block(128);   // ~3 blocks/SM persistent, grid-stride
    nerfacto_kernel<<<grid, block, SMEM_BYTES>>>(
        rs, dirs, cam, aabb, ht,
        rw1, rb1, rw2, rb2,
        dw1, db1, dw2, db2, dw3, db3,
        cw1, cb1, cw2, cb2, cw3, cb3,
        app, out, n, ra);
}

// round 3
// speedup vs baseline: 1.4660x; 1.4660x over previous
#include <cuda_runtime.h>
#include <cstdint>
#include <cmath>

// ---------------------------------------------------------------------------
// NerfactoModel fused forward, CTA-tiled GEMM formulation.
// Tile = 64 samples per CTA iteration; activations feature-major in smem.
// Each thread owns an 8-out x 4-sample fp32x2 accumulator tile.
// ---------------------------------------------------------------------------

typedef unsigned long long ull;

__device__ __forceinline__ ull pk2(float a, float b) {
    ull r;
    asm("mov.b64 %0, {%1, %2};" : "=l"(r) : "f"(a), "f"(b));
    return r;
}
__device__ __forceinline__ void upk2(ull v, float& a, float& b) {
    asm("mov.b64 {%0, %1}, %2;" : "=f"(a), "=f"(b) : "l"(v));
}
__device__ __forceinline__ void fma2(ull& d, ull a, ull b) {
    asm("fma.rn.f32x2 %0, %1, %2, %0;" : "+l"(d) : "l"(a), "l"(b));
}

// ----- shared memory layout (float offsets) -----
#define OFF_DW1 0       // 32*64
#define OFF_DB1 2048    // 64
#define OFF_DW2 2112    // 64*64
#define OFF_DB2 6208    // 64
#define OFF_DW3 6272    // 64*16
#define OFF_DB3 7296    // 16
#define OFF_RW1 7312    // 3*16
#define OFF_RB1 7360    // 16
#define OFF_RW2 7376    // 16*16
#define OFF_RB2 7632    // 16
#define OFF_CW1 7648    // 63*64
#define OFF_CB1 11680   // 64
#define OFF_CW2 11744   // 64*64
#define OFF_CB2 15840   // 64
#define OFF_CW3 15904   // 64*3
#define OFF_CB3 16096   // 3
#define OFF_A   16100   // 64*64 activation buffer A   (16B aligned: 16100*4 % 16 == 0)
#define OFF_B   20196   // 64*64 activation buffer B
#define OFF_OUT 24292   // 64*19 output staging
#define SMEM_FLOATS (24292 + 1216)
#define SMEM_BYTES  (SMEM_FLOATS * 4)

#define TS 64           // samples per tile
#define NT 128          // threads per CTA

struct ResArr { int r[16]; };

// GEMM: Y[64 x TS] = act( W[K x 64]^rows . X[K x TS] + bias ), all smem.
// Thread tiling: 16 sample-groups (4 samples) x 8 out-groups (8 outs).
template<int K, bool RELU>
__device__ __forceinline__ void gemm64(const float* __restrict__ X,
                                       const float* __restrict__ W,
                                       const float* __restrict__ Bs,
                                       float* __restrict__ Y, int tid)
{
    const int sg = tid & 15, og = tid >> 4;
    const float* Xp = X + 4 * sg;
    const float* Wp = W + 8 * og;
    ull acc[16];
    {
        const ulonglong2* bb = reinterpret_cast<const ulonglong2*>(Bs + 8 * og);
        ulonglong2 b0 = bb[0], b1 = bb[1];
        ull bp[4] = { b0.x, b0.y, b1.x, b1.y };
#pragma unroll
        for (int op = 0; op < 4; ++op)
#pragma unroll
            for (int s = 0; s < 4; ++s) acc[op * 4 + s] = bp[op];
    }
#pragma unroll 4
    for (int k = 0; k < K; ++k) {
        float4 xv = *reinterpret_cast<const float4*>(Xp + k * 64);
        ulonglong2 wa = *reinterpret_cast<const ulonglong2*>(Wp + k * 64);
        ulonglong2 wb = *reinterpret_cast<const ulonglong2*>(Wp + k * 64 + 4);
        ull xs[4] = { pk2(xv.x, xv.x), pk2(xv.y, xv.y),
                      pk2(xv.z, xv.z), pk2(xv.w, xv.w) };
        ull wp_[4] = { wa.x, wa.y, wb.x, wb.y };
#pragma unroll
        for (int op = 0; op < 4; ++op)
#pragma unroll
            for (int s = 0; s < 4; ++s)
                fma2(acc[op * 4 + s], wp_[op], xs[s]);
    }
#pragma unroll
    for (int op = 0; op < 4; ++op)
#pragma unroll
        for (int s = 0; s < 4; ++s) {
            float v0, v1; upk2(acc[op * 4 + s], v0, v1);
            if (RELU) { v0 = fmaxf(v0, 0.0f); v1 = fmaxf(v1, 0.0f); }
            const int j = 8 * og + 2 * op, c = 4 * sg + s;
            Y[j * 64 + c]       = v0;
            Y[(j + 1) * 64 + c] = v1;
        }
}

// L3: dfeat[16 x TS] = X(h2) . dens_w3 + b3.  Run by 64 threads (tid2 in 0..63).
// out 0 -> density (relu) into OUT[:,3]; outs 1..15 -> geo into OUT[:,4..18]
// and into CIN rows 0..14 (buffer Bcin).
__device__ __forceinline__ void gemm16_l3(const float* __restrict__ X,
                                          const float* __restrict__ W,
                                          const float* __restrict__ Bs,
                                          float* __restrict__ Bcin,
                                          float* __restrict__ OUT, int tid2)
{
    const int sg = tid2 & 15, og = tid2 >> 4;   // og 0..3, 4 outs each
    const float* Xp = X + 4 * sg;
    const float* Wp = W + 4 * og;
    ull acc[8];
    {
        const ulonglong2* bb = reinterpret_cast<const ulonglong2*>(Bs + 4 * og);
        ulonglong2 b = bb[0];
#pragma unroll
        for (int s = 0; s < 4; ++s) { acc[s] = b.x; acc[4 + s] = b.y; }
    }
#pragma unroll 4
    for (int k = 0; k < 64; ++k) {
        float4 xv = *reinterpret_cast<const float4*>(Xp + k * 64);
        ulonglong2 wa = *reinterpret_cast<const ulonglong2*>(Wp + k * 16);
        ull xs[4] = { pk2(xv.x, xv.x), pk2(xv.y, xv.y),
                      pk2(xv.z, xv.z), pk2(xv.w, xv.w) };
#pragma unroll
        for (int s = 0; s < 4; ++s) {
            fma2(acc[s],     wa.x, xs[s]);
            fma2(acc[4 + s], wa.y, xs[s]);
        }
    }
#pragma unroll
    for (int op = 0; op < 2; ++op)
#pragma unroll
        for (int s = 0; s < 4; ++s) {
            float v0, v1; upk2(acc[op * 4 + s], v0, v1);
            const int j = 4 * og + 2 * op, c = 4 * sg + s;
            if (j == 0) OUT[c * 19 + 3] = fmaxf(v0, 0.0f);
            else { OUT[c * 19 + 3 + j] = v0; Bcin[(j - 1) * 64 + c] = v0; }
            OUT[c * 19 + 3 + j + 1] = v1;
            Bcin[j * 64 + c] = v1;          // (j+1)-1 = j
        }
}

__device__ __forceinline__ void cpy(float* dst, const float* src, int n) {
    for (int t = threadIdx.x; t < n; t += NT) dst[t] = src[t];
}

__global__ void __launch_bounds__(NT) nerfacto_kernel(
    const float* __restrict__ rs, const float* __restrict__ dirs,
    const int*   __restrict__ cam, const float* __restrict__ aabb,
    const float* __restrict__ ht,
    const float* __restrict__ rw1, const float* __restrict__ rb1,
    const float* __restrict__ rw2, const float* __restrict__ rb2,
    const float* __restrict__ dw1, const float* __restrict__ db1,
    const float* __restrict__ dw2, const float* __restrict__ db2,
    const float* __restrict__ dw3, const float* __restrict__ db3,
    const float* __restrict__ cw1, const float* __restrict__ cb1,
    const float* __restrict__ cw2, const float* __restrict__ cb2,
    const float* __restrict__ cw3, const float* __restrict__ cb3,
    const float* __restrict__ app,
    float* __restrict__ out, int n, ResArr RA)
{
    extern __shared__ float sw[];
    cpy(sw + OFF_DW1, dw1, 2048); cpy(sw + OFF_DB1, db1, 64);
    cpy(sw + OFF_DW2, dw2, 4096); cpy(sw + OFF_DB2, db2, 64);
    cpy(sw + OFF_DW3, dw3, 1024); cpy(sw + OFF_DB3, db3, 16);
    cpy(sw + OFF_RW1, rw1, 48);   cpy(sw + OFF_RB1, rb1, 16);
    cpy(sw + OFF_RW2, rw2, 256);  cpy(sw + OFF_RB2, rb2, 16);
    cpy(sw + OFF_CW1, cw1, 4032); cpy(sw + OFF_CB1, cb1, 64);
    cpy(sw + OFF_CW2, cw2, 4096); cpy(sw + OFF_CB2, cb2, 64);
    cpy(sw + OFF_CW3, cw3, 192);  cpy(sw + OFF_CB3, cb3, 3);
    __syncthreads();

    float* sA   = sw + OFF_A;
    float* sB   = sw + OFF_B;
    float* sOUT = sw + OFF_OUT;

    const float a0x = __ldg(aabb + 0), a0y = __ldg(aabb + 1), a0z = __ldg(aabb + 2);
    const float idx_ = __ldg(aabb + 3) - a0x;
    const float idy_ = __ldg(aabb + 4) - a0y;
    const float idz_ = __ldg(aabb + 5) - a0z;
    const float2* htp = reinterpret_cast<const float2*>(ht);

    const int tid = threadIdx.x;
    const int ntiles = (n + TS - 1) / TS;

    for (int tile = blockIdx.x; tile < ntiles; tile += gridDim.x) {
        const int i0 = tile * TS;

        // ---- prefetch dirs + camera index for the dir-MLP half ----
        float dvx = 0.f, dvy = 0.f, dvz = 0.f; int ci = 0;
        if (tid < TS) {
            int si = i0 + tid; if (si >= n) si = n - 1;
            dvx = __ldg(dirs + 3 * si + 0);
            dvy = __ldg(dirs + 3 * si + 1);
            dvz = __ldg(dirs + 3 * si + 2);
            ci  = __ldg(cam + si);
        }

        // ---- P1: hash encode into sA rows 0..31 (feature-major) ----
        {
            const int s = tid >> 1;
            int i = i0 + s; if (i >= n) i = n - 1;
            const float px = fminf(fmaxf((__ldg(rs + 3 * i + 0) - a0x) / idx_, 0.0f), 1.0f);
            const float py = fminf(fmaxf((__ldg(rs + 3 * i + 1) - a0y) / idy_, 0.0f), 1.0f);
            const float pz = fminf(fmaxf((__ldg(rs + 3 * i + 2) - a0z) / idz_, 0.0f), 1.0f);
            const int lb = (tid & 1) * 8;
#pragma unroll
            for (int q = 0; q < 8; ++q) {
                const int l = lb + q;
                const int r = RA.r[l];
                const float rf = (float)(r - 1);
                int cx = (int)floorf(px * rf);
                int cy = (int)floorf(py * rf);
                int cz = (int)floorf(pz * rf);
                cx = min(max(cx, 0), r - 1);
                cy = min(max(cy, 0), r - 1);
                cz = min(max(cz, 0), r - 1);
                const unsigned h = ((unsigned)cx + (unsigned)cy * 2481u
                                    + (unsigned)cz * 1941u) & 4095u;
                const float2 f = __ldg(htp + l * 4096 + h);
                sA[(2 * l)     * 64 + s] = f.x;
                sA[(2 * l + 1) * 64 + s] = f.y;
            }
        }
        __syncthreads();

        // ---- density L1: sB = relu(W1 . enc) ----
        gemm64<32, true>(sA, sw + OFF_DW1, sw + OFF_DB1, sB, tid);
        __syncthreads();
        // ---- density L2: sA = relu(W2 . h1) ----
        gemm64<64, true>(sB, sw + OFF_DW2, sw + OFF_DB2, sA, tid);
        __syncthreads();

        // ---- split phase: warps 0-1 dir MLP + appearance; warps 2-3 L3 ----
        if (tid < TS) {
            const int s = tid;
            // appearance gather (LDGs issued first, consumed after dir MLP)
            const float4* ap4 = reinterpret_cast<const float4*>(app + (size_t)ci * 32);
            float4 ap[8];
#pragma unroll
            for (int q = 0; q < 8; ++q) ap[q] = __ldg(ap4 + q);
            // dir MLP
            float h[16];
#pragma unroll
            for (int j = 0; j < 16; ++j) h[j] = sw[OFF_RB1 + j];
            const float dv[3] = { dvx, dvy, dvz };
#pragma unroll
            for (int k = 0; k < 3; ++k)
#pragma unroll
                for (int j = 0; j < 16; ++j)
                    h[j] = fmaf(dv[k], sw[OFF_RW1 + k * 16 + j], h[j]);
#pragma unroll
            for (int j = 0; j < 16; ++j) h[j] = fmaxf(h[j], 0.0f);
#pragma unroll
            for (int j = 0; j < 16; ++j) {
                float a = sw[OFF_RB2 + j];
#pragma unroll
                for (int k = 0; k < 16; ++k)
                    a = fmaf(h[k], sw[OFF_RW2 + k * 16 + j], a);
                sB[(15 + j) * 64 + s] = a;        // CIN rows 15..30 = edir
            }
#pragma unroll
            for (int q = 0; q < 8; ++q) {         // CIN rows 31..62 = app
                sB[(31 + 4 * q + 0) * 64 + s] = ap[q].x;
                sB[(31 + 4 * q + 1) * 64 + s] = ap[q].y;
                sB[(31 + 4 * q + 2) * 64 + s] = ap[q].z;
                sB[(31 + 4 * q + 3) * 64 + s] = ap[q].w;
            }
        } else {
            gemm16_l3(sA, sw + OFF_DW3, sw + OFF_DB3, sB, sOUT, tid - TS);
        }
        __syncthreads();

        // ---- color L1: sA = relu(CW1 . cin[63]) ----
        gemm64<63, true>(sB, sw + OFF_CW1, sw + OFF_CB1, sA, tid);
        __syncthreads();
        // ---- color L2: sB = relu(CW2 . c1) ----
        gemm64<64, true>(sA, sw + OFF_CW2, sw + OFF_CB2, sB, tid);
        __syncthreads();

        // ---- color L3 (64->3) + sigmoid ----
        if (tid < TS) {
            const int s = tid;
            float a0 = sw[OFF_CB3 + 0], a1 = sw[OFF_CB3 + 1], a2 = sw[OFF_CB3 + 2];
#pragma unroll 8
            for (int k = 0; k < 64; ++k) {
                const float x = sB[k * 64 + s];
                a0 = fmaf(x, sw[OFF_CW3 + k * 3 + 0], a0);
                a1 = fmaf(x, sw[OFF_CW3 + k * 3 + 1], a1);
                a2 = fmaf(x, sw[OFF_CW3 + k * 3 + 2], a2);
            }
            sOUT[s * 19 + 0] = 1.0f / (1.0f + expf(-a0));
            sOUT[s * 19 + 1] = 1.0f / (1.0f + expf(-a1));
            sOUT[s * 19 + 2] = 1.0f / (1.0f + expf(-a2));
        }
        __syncthreads();

        // ---- coalesced store of the 64x19 tile ----
        const int rem = n - i0;
        if (rem >= TS) {
            float4* dst = reinterpret_cast<float4*>(out + (size_t)i0 * 19);
            const float4* src = reinterpret_cast<const float4*>(sOUT);
            for (int j = tid; j < (TS * 19) / 4; j += NT) dst[j] = src[j];
        } else {
            const int cnt = rem * 19;
            for (int j = tid; j < cnt; j += NT) out[(size_t)i0 * 19 + j] = sOUT[j];
        }
        // no sync needed: next P1/prefetch touch only sA/regs; sOUT rewritten
        // only after >=2 later syncs.
    }
}

extern "C" void kernel_launch(void* const* d_in, const int* in_sizes, int n_in,
                              void* d_out, int out_size) {
    const float* rs   = (const float*)d_in[0];
    const float* dirs = (const float*)d_in[1];
    const int*   cam  = (const int*)d_in[2];
    const float* aabb = (const float*)d_in[3];
    const float* ht   = (const float*)d_in[4];
    const float* rw1  = (const float*)d_in[5];
    const float* rb1  = (const float*)d_in[6];
    const float* rw2  = (const float*)d_in[7];
    const float* rb2  = (const float*)d_in[8];
    const float* dw1  = (const float*)d_in[9];
    const float* db1  = (const float*)d_in[10];
    const float* dw2  = (const float*)d_in[11];
    const float* db2  = (const float*)d_in[12];
    const float* dw3  = (const float*)d_in[13];
    const float* db3  = (const float*)d_in[14];
    const float* cw1  = (const float*)d_in[15];
    const float* cb1  = (const float*)d_in[16];
    const float* cw2  = (const float*)d_in[17];
    const float* cb2  = (const float*)d_in[18];
    const float* cw3  = (const float*)d_in[19];
    const float* cb3  = (const float*)d_in[20];
    const float* app  = (const float*)d_in[21];
    float* out = (float*)d_out;

    const int n = in_sizes[0] / 3;

    ResArr ra;
    double growth = exp((log(2048.0) - log(16.0)) / 15.0);
    for (int i = 0; i < 16; ++i)
        ra.r[i] = (int)(16.0 * pow(growth, (double)i));

    cudaFuncSetAttribute(nerfacto_kernel,
                         cudaFuncAttributeMaxDynamicSharedMemorySize, SMEM_BYTES);

    dim3 grid(296), block(NT);   // 2 CTAs/SM (smem-limited), persistent
    nerfacto_kernel<<<grid, block, SMEM_BYTES>>>(
        rs, dirs, cam, aabb, ht,
        rw1, rb1, rw2, rb2,
        dw1, db1, dw2, db2, dw3, db3,
        cw1, cb1, cw2, cb2, cw3, cb3,
        app, out, n, ra);
}

// round 5
// speedup vs baseline: 3.4262x; 2.3371x over previous
#include <cuda_runtime.h>
#include <cuda_bf16.h>
#include <cstdint>
#include <cmath>

typedef unsigned int u32;

#define NT 256
#define TS 256
#define ROWB 144          // bytes per activation/weight row (72 bf16)

// ---- smem byte offsets ----
#define SM_WD1H 0
#define SM_WD1L 9216
#define SM_WD2H 18432
#define SM_WD2L 27648
#define SM_WD3H 36864     // 16 rows
#define SM_WD3L 39168
#define SM_WC1H 41472
#define SM_WC1L 50688
#define SM_WC2H 59904
#define SM_WC2L 69120
#define SM_DB1  78336
#define SM_DB2  78592
#define SM_DB3  78848
#define SM_CB1  78912
#define SM_CB2  79168
#define SM_CB3  79424
#define SM_RW1  79440
#define SM_RB1  79632
#define SM_RW2  79696
#define SM_RB2  80720
#define SM_CW3  80784
#define SM_AH   81664     // 256 rows x 144B
#define SM_AL   118528
#define SMEM_BYTES 155392

__device__ __forceinline__ u32 pk2bf(float vlo, float vhi) {
    u32 r; asm("cvt.rn.bf16x2.f32 %0, %1, %2;" : "=r"(r) : "f"(vhi), "f"(vlo));
    return r;
}
__device__ __forceinline__ void ldsm4(u32 addr, u32& r0, u32& r1, u32& r2, u32& r3) {
    asm volatile("ldmatrix.sync.aligned.m8n8.x4.shared.b16 {%0,%1,%2,%3}, [%4];"
                 : "=r"(r0), "=r"(r1), "=r"(r2), "=r"(r3) : "r"(addr) : "memory");
}
__device__ __forceinline__ void ldsm2(u32 addr, u32& r0, u32& r1) {
    asm volatile("ldmatrix.sync.aligned.m8n8.x2.shared.b16 {%0,%1}, [%2];"
                 : "=r"(r0), "=r"(r1) : "r"(addr) : "memory");
}
__device__ __forceinline__ void mmab(float* c, u32 a0, u32 a1, u32 a2, u32 a3,
                                     u32 b0, u32 b1) {
    asm("mma.sync.aligned.m16n8k16.row.col.f32.bf16.bf16.f32 "
        "{%0,%1,%2,%3},{%4,%5,%6,%7},{%8,%9},{%0,%1,%2,%3};"
        : "+f"(c[0]), "+f"(c[1]), "+f"(c[2]), "+f"(c[3])
        : "r"(a0), "r"(a1), "r"(a2), "r"(a3), "r"(b0), "r"(b1));
}

// GEMM: acc[2*NTL][4] += split-bf16( A[warp rows] * W^T ).  All smem.
template<int KT, int NTL>
__device__ __forceinline__ void do_gemm(u32 aH, u32 aL, u32 wH, u32 wL,
                                        int lane, int warp, float (*acc)[4]) {
#pragma unroll
    for (int t = 0; t < 2 * NTL; ++t) {
        acc[t][0] = 0.f; acc[t][1] = 0.f; acc[t][2] = 0.f; acc[t][3] = 0.f;
    }
    const u32 aOff = (u32)(warp * 32 + (lane & 15)) * ROWB + (u32)(lane >> 4) * 16;
    const u32 bOff = (u32)(lane & 7) * ROWB + (u32)((lane >> 3) & 1) * 16;
#pragma unroll
    for (int kt = 0; kt < KT; ++kt) {
        u32 ah0, ah1, ah2, ah3, ah4, ah5, ah6, ah7;
        u32 al0, al1, al2, al3, al4, al5, al6, al7;
        ldsm4(aH + aOff + kt * 32, ah0, ah1, ah2, ah3);
        ldsm4(aH + aOff + 16 * ROWB + kt * 32, ah4, ah5, ah6, ah7);
        ldsm4(aL + aOff + kt * 32, al0, al1, al2, al3);
        ldsm4(aL + aOff + 16 * ROWB + kt * 32, al4, al5, al6, al7);
#pragma unroll
        for (int nt = 0; nt < NTL; ++nt) {
            u32 bh0, bh1, bl0, bl1;
            ldsm2(wH + bOff + (u32)(nt * 8) * ROWB + kt * 32, bh0, bh1);
            ldsm2(wL + bOff + (u32)(nt * 8) * ROWB + kt * 32, bl0, bl1);
            mmab(acc[nt],       ah0, ah1, ah2, ah3, bh0, bh1);
            mmab(acc[NTL + nt], ah4, ah5, ah6, ah7, bh0, bh1);
            mmab(acc[nt],       ah0, ah1, ah2, ah3, bl0, bl1);
            mmab(acc[NTL + nt], ah4, ah5, ah6, ah7, bl0, bl1);
            mmab(acc[nt],       al0, al1, al2, al3, bh0, bh1);
            mmab(acc[NTL + nt], al4, al5, al6, al7, bh0, bh1);
        }
    }
}

// Epilogue: bias + relu, write back as bf16 hi/lo rows.
template<int NTL>
__device__ __forceinline__ void epi_bf16(const float (*acc)[4], const float* bias,
                                         char* smc, int lane, int warp) {
    const int r0 = warp * 32 + (lane >> 2);
    const int cb = (lane & 3) * 2;
#pragma unroll
    for (int mt = 0; mt < 2; ++mt) {
#pragma unroll
        for (int nt = 0; nt < NTL; ++nt) {
            const int c = 8 * nt + cb;
            const float b0 = bias[c], b1 = bias[c + 1];
            const float* a = acc[mt * NTL + nt];
            float v0 = fmaxf(a[0] + b0, 0.f), v1 = fmaxf(a[1] + b1, 0.f);
            float v2 = fmaxf(a[2] + b0, 0.f), v3 = fmaxf(a[3] + b1, 0.f);
            const int rA = r0 + 16 * mt, rB = rA + 8;
            u32 h01 = pk2bf(v0, v1), h23 = pk2bf(v2, v3);
            float f0 = __uint_as_float(h01 << 16);
            float f1 = __uint_as_float(h01 & 0xffff0000u);
            float f2 = __uint_as_float(h23 << 16);
            float f3 = __uint_as_float(h23 & 0xffff0000u);
            u32 l01 = pk2bf(v0 - f0, v1 - f1), l23 = pk2bf(v2 - f2, v3 - f3);
            *(u32*)(smc + SM_AH + rA * ROWB + c * 2) = h01;
            *(u32*)(smc + SM_AH + rB * ROWB + c * 2) = h23;
            *(u32*)(smc + SM_AL + rA * ROWB + c * 2) = l01;
            *(u32*)(smc + SM_AL + rB * ROWB + c * 2) = l23;
        }
    }
}

// Write one activation row (NC8 chunks of 8 cols) as bf16 hi/lo.
__device__ __forceinline__ void write_row(char* smc, int s, const float* v, int nch) {
    for (int ch = 0; ch < nch; ++ch) {
        u32 h[4], l[4];
#pragma unroll
        for (int q = 0; q < 4; ++q) {
            float x0 = v[8 * ch + 2 * q], x1 = v[8 * ch + 2 * q + 1];
            u32 hp = pk2bf(x0, x1);
            float f0 = __uint_as_float(hp << 16);
            float f1 = __uint_as_float(hp & 0xffff0000u);
            h[q] = hp;
            l[q] = pk2bf(x0 - f0, x1 - f1);
        }
        *(uint4*)(smc + SM_AH + s * ROWB + ch * 16) = make_uint4(h[0], h[1], h[2], h[3]);
        *(uint4*)(smc + SM_AL + s * ROWB + ch * 16) = make_uint4(l[0], l[1], l[2], l[3]);
    }
}

// fp32 W[k][n] (global) -> smem [n][72] bf16 hi/lo, K padded to 64.
__device__ void prep_B(char* smc, const float* W, int Kreal, int Nrows, int stride,
                       int offH, int offL) {
    for (int idx = threadIdx.x; idx < Nrows * 64; idx += NT) {
        int nr = idx >> 6, k = idx & 63;
        float x = (k < Kreal) ? __ldg(W + k * stride + nr) : 0.0f;
        u32 p = pk2bf(x, x);
        float fh = __uint_as_float(p << 16);
        u32 pl = pk2bf(x - fh, x - fh);
        *(unsigned short*)(smc + offH + nr * ROWB + k * 2) = (unsigned short)(p & 0xffffu);
        *(unsigned short*)(smc + offL + nr * ROWB + k * 2) = (unsigned short)(pl & 0xffffu);
    }
}
__device__ void cpyf(char* smc, int off, const float* src, int nf) {
    float* d = (float*)(smc + off);
    for (int t = threadIdx.x; t < nf; t += NT) d[t] = __ldg(src + t);
}

struct ResArr { int r[16]; };

__global__ void __launch_bounds__(NT, 1) nerf_mma_kernel(
    const float* __restrict__ rs, const float* __restrict__ dirs,
    const int*   __restrict__ cam, const float* __restrict__ aabb,
    const float* __restrict__ ht,
    const float* __restrict__ rw1, const float* __restrict__ rb1,
    const float* __restrict__ rw2, const float* __restrict__ rb2,
    const float* __restrict__ dw1, const float* __restrict__ db1,
    const float* __restrict__ dw2, const float* __restrict__ db2,
    const float* __restrict__ dw3, const float* __restrict__ db3,
    const float* __restrict__ cw1, const float* __restrict__ cb1,
    const float* __restrict__ cw2, const float* __restrict__ cb2,
    const float* __restrict__ cw3, const float* __restrict__ cb3,
    const float* __restrict__ app,
    float* __restrict__ out, int n, ResArr RA)
{
    extern __shared__ __align__(128) char smc[];
    u32 sb;
    asm("{ .reg .u64 t; cvta.to.shared.u64 t, %1; cvt.u32.u64 %0, t; }"
        : "=r"(sb) : "l"(smc));

    // ---- one-time weight prep ----
    prep_B(smc, dw1, 32, 64, 64, SM_WD1H, SM_WD1L);
    prep_B(smc, dw2, 64, 64, 64, SM_WD2H, SM_WD2L);
    prep_B(smc, dw3, 64, 16, 16, SM_WD3H, SM_WD3L);
    prep_B(smc, cw1, 63, 64, 64, SM_WC1H, SM_WC1L);
    prep_B(smc, cw2, 64, 64, 64, SM_WC2H, SM_WC2L);
    cpyf(smc, SM_DB1, db1, 64);  cpyf(smc, SM_DB2, db2, 64);
    cpyf(smc, SM_DB3, db3, 16);  cpyf(smc, SM_CB1, cb1, 64);
    cpyf(smc, SM_CB2, cb2, 64);  cpyf(smc, SM_CB3, cb3, 3);
    cpyf(smc, SM_RW1, rw1, 48);  cpyf(smc, SM_RB1, rb1, 16);
    cpyf(smc, SM_RW2, rw2, 256); cpyf(smc, SM_RB2, rb2, 16);
    cpyf(smc, SM_CW3, cw3, 192);
    __syncthreads();

    const int tid = threadIdx.x, lane = tid & 31, warp = tid >> 5;
    const u32 AHu = sb + SM_AH, ALu = sb + SM_AL;

    const float a0x = __ldg(aabb + 0), a0y = __ldg(aabb + 1), a0z = __ldg(aabb + 2);
    const float ddx = __ldg(aabb + 3) - a0x;
    const float ddy = __ldg(aabb + 4) - a0y;
    const float ddz = __ldg(aabb + 5) - a0z;
    const float2* htp = (const float2*)ht;
    const float* sDB1 = (const float*)(smc + SM_DB1);
    const float* sDB2 = (const float*)(smc + SM_DB2);
    const float* sDB3 = (const float*)(smc + SM_DB3);
    const float* sCB1 = (const float*)(smc + SM_CB1);
    const float* sCB2 = (const float*)(smc + SM_CB2);
    const float* sCB3 = (const float*)(smc + SM_CB3);
    const float* sRW1 = (const float*)(smc + SM_RW1);
    const float* sRB1 = (const float*)(smc + SM_RB1);
    const float* sRW2 = (const float*)(smc + SM_RW2);
    const float* sRB2 = (const float*)(smc + SM_RB2);
    const float* sCW3 = (const float*)(smc + SM_CW3);

    const int ntiles = (n + TS - 1) / TS;

    for (int tile = blockIdx.x; tile < ntiles; tile += gridDim.x) {
        const int i0 = tile * TS;
        int i = i0 + tid; if (i >= n) i = n - 1;

        // ---- hash encode (exact fp32) -> A row (32 cols) ----
        {
            float ev[32];
            const float px = fminf(fmaxf((__ldg(rs + 3*i + 0) - a0x) / ddx, 0.f), 1.f);
            const float py = fminf(fmaxf((__ldg(rs + 3*i + 1) - a0y) / ddy, 0.f), 1.f);
            const float pz = fminf(fmaxf((__ldg(rs + 3*i + 2) - a0z) / ddz, 0.f), 1.f);
#pragma unroll
            for (int l = 0; l < 16; ++l) {
                const int r = RA.r[l];
                const float rf = (float)(r - 1);
                int cx = (int)floorf(px * rf);
                int cy = (int)floorf(py * rf);
                int cz = (int)floorf(pz * rf);
                cx = min(max(cx, 0), r - 1);
                cy = min(max(cy, 0), r - 1);
                cz = min(max(cz, 0), r - 1);
                const unsigned h = ((unsigned)cx + (unsigned)cy * 2481u
                                    + (unsigned)cz * 1941u) & 4095u;
                const float2 f = __ldg(htp + l * 4096 + h);
                ev[2*l] = f.x; ev[2*l + 1] = f.y;
            }
            write_row(smc, tid, ev, 4);
        }
        __syncwarp();

        float acc[16][4];
        // ---- density L1 (K=32) ----
        do_gemm<2, 8>(AHu, ALu, sb + SM_WD1H, sb + SM_WD1L, lane, warp, acc);
        __syncwarp();
        epi_bf16<8>(acc, sDB1, smc, lane, warp);
        __syncwarp();
        // ---- density L2 (K=64) ----
        do_gemm<4, 8>(AHu, ALu, sb + SM_WD2H, sb + SM_WD2L, lane, warp, acc);
        __syncwarp();
        epi_bf16<8>(acc, sDB2, smc, lane, warp);
        __syncwarp();
        // ---- density L3 (64 -> 16), fp32 staging ----
        do_gemm<4, 2>(AHu, ALu, sb + SM_WD3H, sb + SM_WD3L, lane, warp, acc);
        __syncwarp();
        {
            const int r0 = warp * 32 + (lane >> 2);
            const int cb = (lane & 3) * 2;
#pragma unroll
            for (int mt = 0; mt < 2; ++mt)
#pragma unroll
                for (int nt = 0; nt < 2; ++nt) {
                    const int c = 8 * nt + cb;
                    const float b0 = sDB3[c], b1 = sDB3[c + 1];
                    const float* a = acc[mt * 2 + nt];
                    const int rA = r0 + 16 * mt, rB = rA + 8;
                    *(float2*)(smc + SM_AH + rA * ROWB + c * 4) =
                        make_float2(a[0] + b0, a[1] + b1);
                    *(float2*)(smc + SM_AH + rB * ROWB + c * 4) =
                        make_float2(a[2] + b0, a[3] + b1);
                }
        }
        __syncwarp();
        float df[16];
        {
            const float* rowp = (const float*)(smc + SM_AH + tid * ROWB);
#pragma unroll
            for (int j = 0; j < 16; ++j) df[j] = rowp[j];
        }
        __syncwarp();

        // ---- dir MLP (exact fp32) + appearance; build cin row ----
        {
            const float dvx = __ldg(dirs + 3*i + 0);
            const float dvy = __ldg(dirs + 3*i + 1);
            const float dvz = __ldg(dirs + 3*i + 2);
            const int   ci  = __ldg(cam + i);
            float cin[64];
#pragma unroll
            for (int j = 0; j < 15; ++j) cin[j] = df[1 + j];
            float hm[16];
#pragma unroll
            for (int j = 0; j < 16; ++j) hm[j] = sRB1[j];
            const float dv[3] = { dvx, dvy, dvz };
#pragma unroll
            for (int k = 0; k < 3; ++k)
#pragma unroll
                for (int j = 0; j < 16; ++j)
                    hm[j] = fmaf(dv[k], sRW1[k*16 + j], hm[j]);
#pragma unroll
            for (int j = 0; j < 16; ++j) hm[j] = fmaxf(hm[j], 0.0f);
#pragma unroll
            for (int j = 0; j < 16; ++j) {
                float a = sRB2[j];
#pragma unroll
                for (int k = 0; k < 16; ++k)
                    a = fmaf(hm[k], sRW2[k*16 + j], a);
                cin[15 + j] = a;
            }
            const float4* a4 = (const float4*)(app + (size_t)ci * 32);
#pragma unroll
            for (int q = 0; q < 8; ++q) {
                float4 v = __ldg(a4 + q);
                cin[31 + 4*q + 0] = v.x; cin[31 + 4*q + 1] = v.y;
                cin[31 + 4*q + 2] = v.z; cin[31 + 4*q + 3] = v.w;
            }
            cin[63] = 0.0f;
            write_row(smc, tid, cin, 8);
        }
        __syncwarp();
        // ---- color L1 (K=63+pad) ----
        do_gemm<4, 8>(AHu, ALu, sb + SM_WC1H, sb + SM_WC1L, lane, warp, acc);
        __syncwarp();
        epi_bf16<8>(acc, sCB1, smc, lane, warp);
        __syncwarp();
        // ---- color L2 (K=64) -> fp32 staging (bias+relu) ----
        do_gemm<4, 8>(AHu, ALu, sb + SM_WC2H, sb + SM_WC2L, lane, warp, acc);
        __syncwarp();
        {
            const int r0 = warp * 32 + (lane >> 2);
            const int cb = (lane & 3) * 2;
#pragma unroll
            for (int mt = 0; mt < 2; ++mt)
#pragma unroll
                for (int nt = 0; nt < 8; ++nt) {
                    const int c = 8 * nt + cb;
                    const float b0 = sCB2[c], b1 = sCB2[c + 1];
                    const float* a = acc[mt * 8 + nt];
                    float v0 = fmaxf(a[0] + b0, 0.f), v1 = fmaxf(a[1] + b1, 0.f);
                    float v2 = fmaxf(a[2] + b0, 0.f), v3 = fmaxf(a[3] + b1, 0.f);
                    const int rA = r0 + 16 * mt, rB = rA + 8;
                    const int half = (nt < 4) ? SM_AH : SM_AL;
                    const int cc = (nt < 4) ? c : c - 32;
                    *(float2*)(smc + half + rA * ROWB + cc * 4) = make_float2(v0, v1);
                    *(float2*)(smc + half + rB * ROWB + cc * 4) = make_float2(v2, v3);
                }
        }
        __syncwarp();
        // ---- final 64->3 + sigmoid (exact fp32), stage 19-float row ----
        {
            const float* rH = (const float*)(smc + SM_AH + tid * ROWB);
            const float* rL = (const float*)(smc + SM_AL + tid * ROWB);
            float a0 = sCB3[0], a1 = sCB3[1], a2 = sCB3[2];
#pragma unroll 8
            for (int k = 0; k < 32; ++k) {
                const float x = rH[k];
                a0 = fmaf(x, sCW3[3*k + 0], a0);
                a1 = fmaf(x, sCW3[3*k + 1], a1);
                a2 = fmaf(x, sCW3[3*k + 2], a2);
            }
#pragma unroll 8
            for (int k = 0; k < 32; ++k) {
                const float x = rL[k];
                a0 = fmaf(x, sCW3[3*(32+k) + 0], a0);
                a1 = fmaf(x, sCW3[3*(32+k) + 1], a1);
                a2 = fmaf(x, sCW3[3*(32+k) + 2], a2);
            }
            __syncwarp();
            float* orow = (float*)(smc + SM_AH + tid * ROWB);
            orow[0] = 1.0f / (1.0f + expf(-a0));
            orow[1] = 1.0f / (1.0f + expf(-a1));
            orow[2] = 1.0f / (1.0f + expf(-a2));
            orow[3] = fmaxf(df[0], 0.0f);
#pragma unroll
            for (int j = 0; j < 15; ++j) orow[4 + j] = df[1 + j];
        }
        __syncwarp();
        // ---- coalesced per-warp store (32 rows x 19 floats) ----
        {
            const int m = min(TS, n - i0);            // valid samples in tile
            const int vw = min(32, m - warp * 32);    // valid rows this warp
            if (vw > 0) {
                float* gbase = out + (size_t)(i0 + warp * 32) * 19;
                const char* sbase = smc + SM_AH + (warp * 32) * ROWB;
                int s = lane / 19, c = lane % 19;
#pragma unroll
                for (int it = 0; it < 19; ++it) {
                    if (s < vw)
                        gbase[it * 32 + lane] = *(const float*)(sbase + s * ROWB + c * 4);
                    c += 13; s += 1;
                    if (c >= 19) { c -= 19; s += 1; }
                }
            }
        }
        __syncwarp();
    }
}

extern "C" void kernel_launch(void* const* d_in, const int* in_sizes, int n_in,
                              void* d_out, int out_size) {
    const float* rs   = (const float*)d_in[0];
    const float* dirs = (const float*)d_in[1];
    const int*   cam  = (const int*)d_in[2];
    const float* aabb = (const float*)d_in[3];
    const float* ht   = (const float*)d_in[4];
    const float* rw1  = (const float*)d_in[5];
    const float* rb1  = (const float*)d_in[6];
    const float* rw2  = (const float*)d_in[7];
    const float* rb2  = (const float*)d_in[8];
    const float* dw1  = (const float*)d_in[9];
    const float* db1  = (const float*)d_in[10];
    const float* dw2  = (const float*)d_in[11];
    const float* db2  = (const float*)d_in[12];
    const float* dw3  = (const float*)d_in[13];
    const float* db3  = (const float*)d_in[14];
    const float* cw1  = (const float*)d_in[15];
    const float* cb1  = (const float*)d_in[16];
    const float* cw2  = (const float*)d_in[17];
    const float* cb2  = (const float*)d_in[18];
    const float* cw3  = (const float*)d_in[19];
    const float* cb3  = (const float*)d_in[20];
    const float* app  = (const float*)d_in[21];
    float* out = (float*)d_out;

    const int n = in_sizes[0] / 3;

    ResArr ra;
    double growth = exp((log(2048.0) - log(16.0)) / 15.0);
    for (int i = 0; i < 16; ++i)
        ra.r[i] = (int)(16.0 * pow(growth, (double)i));

    cudaFuncSetAttribute(nerf_mma_kernel,
                         cudaFuncAttributeMaxDynamicSharedMemorySize, SMEM_BYTES);

    dim3 grid(148), block(NT);   // 1 CTA/SM persistent, warp-independent tiles
    nerf_mma_kernel<<<grid, block, SMEM_BYTES>>>(
        rs, dirs, cam, aabb, ht,
        rw1, rb1, rw2, rb2,
        dw1, db1, dw2, db2, dw3, db3,
        cw1, cb1, cw2, cb2, cw3, cb3,
        app, out, n, ra);
}

// round 6
// speedup vs baseline: 4.4032x; 1.2852x over previous
#include <cuda_runtime.h>
#include <cuda_fp16.h>
#include <cstdint>
#include <cmath>

typedef unsigned int u32;

#define NT 256
#define TS 256
#define ROWB 144          // bytes per activation/weight row (72 fp16)

// ---- smem byte offsets ----
#define SM_WD1H 0
#define SM_WD2H 9216
#define SM_WD3H 18432
#define SM_WC1H 20736
#define SM_WC2H 29952
#define SM_DB1  39168
#define SM_DB2  39424
#define SM_DB3  39680
#define SM_CB1  39744
#define SM_CB2  40000
#define SM_CB3  40256
#define SM_RW1  40272
#define SM_RB1  40464
#define SM_RW2  40528
#define SM_RB2  41552
#define SM_CW3  41616
#define SM_AH   42496     // 256 rows x 144B
#define SM_AL   79360
#define SMEM_BYTES 116224

// pack two fp32 -> fp16x2 (lo in low half, hi in high half)
__device__ __forceinline__ u32 pk2h(float vlo, float vhi) {
    u32 r; asm("cvt.rn.f16x2.f32 %0, %1, %2;" : "=r"(r) : "f"(vhi), "f"(vlo));
    return r;
}
__device__ __forceinline__ float2 up2h(u32 p) {
    float lo, hi;
    asm("{ .reg .f16 l, h; mov.b32 {l, h}, %2; cvt.f32.f16 %0, l; cvt.f32.f16 %1, h; }"
        : "=f"(lo), "=f"(hi) : "r"(p));
    return make_float2(lo, hi);
}
__device__ __forceinline__ void ldsm4(u32 addr, u32& r0, u32& r1, u32& r2, u32& r3) {
    asm volatile("ldmatrix.sync.aligned.m8n8.x4.shared.b16 {%0,%1,%2,%3}, [%4];"
                 : "=r"(r0), "=r"(r1), "=r"(r2), "=r"(r3) : "r"(addr) : "memory");
}
__device__ __forceinline__ void mmah(float* c, u32 a0, u32 a1, u32 a2, u32 a3,
                                     u32 b0, u32 b1) {
    asm("mma.sync.aligned.m16n8k16.row.col.f32.f16.f16.f32 "
        "{%0,%1,%2,%3},{%4,%5,%6,%7},{%8,%9},{%0,%1,%2,%3};"
        : "+f"(c[0]), "+f"(c[1]), "+f"(c[2]), "+f"(c[3])
        : "r"(a0), "r"(a1), "r"(a2), "r"(a3), "r"(b0), "r"(b1));
}

// GEMM: acc[2*NTL][4] += fp16-2-term( A[warp rows] * W^T ).  All smem.
// A split hi/lo fp16; W single fp16. Weight fragments ldsm4-paired (2 n-tiles).
template<int KT, int NTL>
__device__ __forceinline__ void do_gemm(u32 aH, u32 aL, u32 wH,
                                        int lane, int warp, float (*acc)[4]) {
#pragma unroll
    for (int t = 0; t < 2 * NTL; ++t) {
        acc[t][0] = 0.f; acc[t][1] = 0.f; acc[t][2] = 0.f; acc[t][3] = 0.f;
    }
    const u32 aOff = (u32)(warp * 32 + (lane & 15)) * ROWB + (u32)(lane >> 4) * 16;
    // paired B: row = (lane&7) + ((lane>>4)&1)*8, k-half = (lane>>3)&1
    const u32 bOff = (u32)((lane & 7) + ((lane >> 4) & 1) * 8) * ROWB
                   + (u32)((lane >> 3) & 1) * 16;
#pragma unroll
    for (int kt = 0; kt < KT; ++kt) {
        u32 h00,h01,h02,h03, h10,h11,h12,h13;
        u32 l00,l01,l02,l03, l10,l11,l12,l13;
        ldsm4(aH + aOff + kt * 32,             h00, h01, h02, h03);
        ldsm4(aH + aOff + 16 * ROWB + kt * 32, h10, h11, h12, h13);
        ldsm4(aL + aOff + kt * 32,             l00, l01, l02, l03);
        ldsm4(aL + aOff + 16 * ROWB + kt * 32, l10, l11, l12, l13);
#pragma unroll
        for (int p = 0; p < NTL / 2; ++p) {
            u32 b0, b1, b2, b3;
            ldsm4(wH + bOff + (u32)(p * 16) * ROWB + kt * 32, b0, b1, b2, b3);
            mmah(acc[2*p],           h00, h01, h02, h03, b0, b1);
            mmah(acc[2*p + 1],       h00, h01, h02, h03, b2, b3);
            mmah(acc[NTL + 2*p],     h10, h11, h12, h13, b0, b1);
            mmah(acc[NTL + 2*p + 1], h10, h11, h12, h13, b2, b3);
            mmah(acc[2*p],           l00, l01, l02, l03, b0, b1);
            mmah(acc[2*p + 1],       l00, l01, l02, l03, b2, b3);
            mmah(acc[NTL + 2*p],     l10, l11, l12, l13, b0, b1);
            mmah(acc[NTL + 2*p + 1], l10, l11, l12, l13, b2, b3);
        }
    }
}

// Epilogue: bias + relu, write back as fp16 hi/lo rows.
template<int NTL>
__device__ __forceinline__ void epi_f16(const float (*acc)[4], const float* bias,
                                        char* smc, int lane, int warp) {
    const int r0 = warp * 32 + (lane >> 2);
    const int cb = (lane & 3) * 2;
#pragma unroll
    for (int mt = 0; mt < 2; ++mt) {
#pragma unroll
        for (int nt = 0; nt < NTL; ++nt) {
            const int c = 8 * nt + cb;
            const float b0 = bias[c], b1 = bias[c + 1];
            const float* a = acc[mt * NTL + nt];
            float v0 = fmaxf(a[0] + b0, 0.f), v1 = fmaxf(a[1] + b1, 0.f);
            float v2 = fmaxf(a[2] + b0, 0.f), v3 = fmaxf(a[3] + b1, 0.f);
            const int rA = r0 + 16 * mt, rB = rA + 8;
            u32 h01 = pk2h(v0, v1), h23 = pk2h(v2, v3);
            float2 f01 = up2h(h01), f23 = up2h(h23);
            u32 l01 = pk2h(v0 - f01.x, v1 - f01.y);
            u32 l23 = pk2h(v2 - f23.x, v3 - f23.y);
            *(u32*)(smc + SM_AH + rA * ROWB + c * 2) = h01;
            *(u32*)(smc + SM_AH + rB * ROWB + c * 2) = h23;
            *(u32*)(smc + SM_AL + rA * ROWB + c * 2) = l01;
            *(u32*)(smc + SM_AL + rB * ROWB + c * 2) = l23;
        }
    }
}

// Write one activation row (nch chunks of 8 cols) as fp16 hi/lo.
__device__ __forceinline__ void write_row(char* smc, int s, const float* v, int nch) {
    for (int ch = 0; ch < nch; ++ch) {
        u32 h[4], l[4];
#pragma unroll
        for (int q = 0; q < 4; ++q) {
            float x0 = v[8 * ch + 2 * q], x1 = v[8 * ch + 2 * q + 1];
            u32 hp = pk2h(x0, x1);
            float2 f = up2h(hp);
            h[q] = hp;
            l[q] = pk2h(x0 - f.x, x1 - f.y);
        }
        *(uint4*)(smc + SM_AH + s * ROWB + ch * 16) = make_uint4(h[0], h[1], h[2], h[3]);
        *(uint4*)(smc + SM_AL + s * ROWB + ch * 16) = make_uint4(l[0], l[1], l[2], l[3]);
    }
}

// fp32 W[k][n] (global) -> smem [n][72] fp16, K padded to 64.
__device__ void prep_B(char* smc, const float* W, int Kreal, int Nrows, int stride,
                       int offH) {
    for (int idx = threadIdx.x; idx < Nrows * 64; idx += NT) {
        int nr = idx >> 6, k = idx & 63;
        float x = (k < Kreal) ? __ldg(W + k * stride + nr) : 0.0f;
        u32 p = pk2h(x, x);
        *(unsigned short*)(smc + offH + nr * ROWB + k * 2) = (unsigned short)(p & 0xffffu);
    }
}
__device__ void cpyf(char* smc, int off, const float* src, int nf) {
    float* d = (float*)(smc + off);
    for (int t = threadIdx.x; t < nf; t += NT) d[t] = __ldg(src + t);
}

struct ResArr { int r[16]; };

__global__ void __launch_bounds__(NT, 1) nerf_h2_kernel(
    const float* __restrict__ rs, const float* __restrict__ dirs,
    const int*   __restrict__ cam, const float* __restrict__ aabb,
    const float* __restrict__ ht,
    const float* __restrict__ rw1, const float* __restrict__ rb1,
    const float* __restrict__ rw2, const float* __restrict__ rb2,
    const float* __restrict__ dw1, const float* __restrict__ db1,
    const float* __restrict__ dw2, const float* __restrict__ db2,
    const float* __restrict__ dw3, const float* __restrict__ db3,
    const float* __restrict__ cw1, const float* __restrict__ cb1,
    const float* __restrict__ cw2, const float* __restrict__ cb2,
    const float* __restrict__ cw3, const float* __restrict__ cb3,
    const float* __restrict__ app,
    float* __restrict__ out, int n, ResArr RA)
{
    extern __shared__ __align__(128) char smc[];
    u32 sb;
    asm("{ .reg .u64 t; cvta.to.shared.u64 t, %1; cvt.u32.u64 %0, t; }"
        : "=r"(sb) : "l"(smc));

    // ---- one-time weight prep ----
    prep_B(smc, dw1, 32, 64, 64, SM_WD1H);
    prep_B(smc, dw2, 64, 64, 64, SM_WD2H);
    prep_B(smc, dw3, 64, 16, 16, SM_WD3H);
    prep_B(smc, cw1, 63, 64, 64, SM_WC1H);
    prep_B(smc, cw2, 64, 64, 64, SM_WC2H);
    cpyf(smc, SM_DB1, db1, 64);  cpyf(smc, SM_DB2, db2, 64);
    cpyf(smc, SM_DB3, db3, 16);  cpyf(smc, SM_CB1, cb1, 64);
    cpyf(smc, SM_CB2, cb2, 64);  cpyf(smc, SM_CB3, cb3, 3);
    cpyf(smc, SM_RW1, rw1, 48);  cpyf(smc, SM_RB1, rb1, 16);
    cpyf(smc, SM_RW2, rw2, 256); cpyf(smc, SM_RB2, rb2, 16);
    cpyf(smc, SM_CW3, cw3, 192);
    __syncthreads();

    const int tid = threadIdx.x, lane = tid & 31, warp = tid >> 5;
    const u32 AHu = sb + SM_AH, ALu = sb + SM_AL;

    const float a0x = __ldg(aabb + 0), a0y = __ldg(aabb + 1), a0z = __ldg(aabb + 2);
    const float ddx = __ldg(aabb + 3) - a0x;
    const float ddy = __ldg(aabb + 4) - a0y;
    const float ddz = __ldg(aabb + 5) - a0z;
    const float2* htp = (const float2*)ht;
    const float* sDB1 = (const float*)(smc + SM_DB1);
    const float* sDB2 = (const float*)(smc + SM_DB2);
    const float* sDB3 = (const float*)(smc + SM_DB3);
    const float* sCB1 = (const float*)(smc + SM_CB1);
    const float* sCB2 = (const float*)(smc + SM_CB2);
    const float* sCB3 = (const float*)(smc + SM_CB3);
    const float* sRW1 = (const float*)(smc + SM_RW1);
    const float* sRB1 = (const float*)(smc + SM_RB1);
    const float* sRW2 = (const float*)(smc + SM_RW2);
    const float* sRB2 = (const float*)(smc + SM_RB2);
    const float* sCW3 = (const float*)(smc + SM_CW3);

    const int ntiles = (n + TS - 1) / TS;

    for (int tile = blockIdx.x; tile < ntiles; tile += gridDim.x) {
        const int i0 = tile * TS;
        int i = i0 + tid; if (i >= n) i = n - 1;

        // ---- hash encode (exact fp32) -> A row (32 cols) ----
        {
            float ev[32];
            const float px = fminf(fmaxf((__ldg(rs + 3*i + 0) - a0x) / ddx, 0.f), 1.f);
            const float py = fminf(fmaxf((__ldg(rs + 3*i + 1) - a0y) / ddy, 0.f), 1.f);
            const float pz = fminf(fmaxf((__ldg(rs + 3*i + 2) - a0z) / ddz, 0.f), 1.f);
#pragma unroll
            for (int l = 0; l < 16; ++l) {
                const int r = RA.r[l];
                const float rf = (float)(r - 1);
                int cx = (int)floorf(px * rf);
                int cy = (int)floorf(py * rf);
                int cz = (int)floorf(pz * rf);
                cx = min(max(cx, 0), r - 1);
                cy = min(max(cy, 0), r - 1);
                cz = min(max(cz, 0), r - 1);
                const unsigned h = ((unsigned)cx + (unsigned)cy * 2481u
                                    + (unsigned)cz * 1941u) & 4095u;
                const float2 f = __ldg(htp + l * 4096 + h);
                ev[2*l] = f.x; ev[2*l + 1] = f.y;
            }
            write_row(smc, tid, ev, 4);
        }
        __syncwarp();

        float acc[16][4];
        // ---- density L1 (K=32) ----
        do_gemm<2, 8>(AHu, ALu, sb + SM_WD1H, lane, warp, acc);
        __syncwarp();
        epi_f16<8>(acc, sDB1, smc, lane, warp);
        __syncwarp();
        // ---- density L2 (K=64) ----
        do_gemm<4, 8>(AHu, ALu, sb + SM_WD2H, lane, warp, acc);
        __syncwarp();
        epi_f16<8>(acc, sDB2, smc, lane, warp);
        __syncwarp();
        // ---- density L3 (64 -> 16), fp32 staging ----
        do_gemm<4, 2>(AHu, ALu, sb + SM_WD3H, lane, warp, acc);
        __syncwarp();
        {
            const int r0 = warp * 32 + (lane >> 2);
            const int cb = (lane & 3) * 2;
#pragma unroll
            for (int mt = 0; mt < 2; ++mt)
#pragma unroll
                for (int nt = 0; nt < 2; ++nt) {
                    const int c = 8 * nt + cb;
                    const float b0 = sDB3[c], b1 = sDB3[c + 1];
                    const float* a = acc[mt * 2 + nt];
                    const int rA = r0 + 16 * mt, rB = rA + 8;
                    *(float2*)(smc + SM_AH + rA * ROWB + c * 4) =
                        make_float2(a[0] + b0, a[1] + b1);
                    *(float2*)(smc + SM_AH + rB * ROWB + c * 4) =
                        make_float2(a[2] + b0, a[3] + b1);
                }
        }
        __syncwarp();
        float df[16];
        {
            const float* rowp = (const float*)(smc + SM_AH + tid * ROWB);
#pragma unroll
            for (int j = 0; j < 16; ++j) df[j] = rowp[j];
        }
        __syncwarp();

        // ---- dir MLP (exact fp32) + appearance; build cin row ----
        {
            const float dvx = __ldg(dirs + 3*i + 0);
            const float dvy = __ldg(dirs + 3*i + 1);
            const float dvz = __ldg(dirs + 3*i + 2);
            const int   ci  = __ldg(cam + i);
            float cin[64];
#pragma unroll
            for (int j = 0; j < 15; ++j) cin[j] = df[1 + j];
            float hm[16];
#pragma unroll
            for (int j = 0; j < 16; ++j) hm[j] = sRB1[j];
            const float dv[3] = { dvx, dvy, dvz };
#pragma unroll
            for (int k = 0; k < 3; ++k)
#pragma unroll
                for (int j = 0; j < 16; ++j)
                    hm[j] = fmaf(dv[k], sRW1[k*16 + j], hm[j]);
#pragma unroll
            for (int j = 0; j < 16; ++j) hm[j] = fmaxf(hm[j], 0.0f);
#pragma unroll
            for (int j = 0; j < 16; ++j) {
                float a = sRB2[j];
#pragma unroll
                for (int k = 0; k < 16; ++k)
                    a = fmaf(hm[k], sRW2[k*16 + j], a);
                cin[15 + j] = a;
            }
            const float4* a4 = (const float4*)(app + (size_t)ci * 32);
#pragma unroll
            for (int q = 0; q < 8; ++q) {
                float4 v = __ldg(a4 + q);
                cin[31 + 4*q + 0] = v.x; cin[31 + 4*q + 1] = v.y;
                cin[31 + 4*q + 2] = v.z; cin[31 + 4*q + 3] = v.w;
            }
            cin[63] = 0.0f;
            write_row(smc, tid, cin, 8);
        }
        __syncwarp();
        // ---- color L1 (K=63+pad) ----
        do_gemm<4, 8>(AHu, ALu, sb + SM_WC1H, lane, warp, acc);
        __syncwarp();
        epi_f16<8>(acc, sCB1, smc, lane, warp);
        __syncwarp();
        // ---- color L2 (K=64) -> fp32 staging (bias+relu) ----
        do_gemm<4, 8>(AHu, ALu, sb + SM_WC2H, lane, warp, acc);
        __syncwarp();
        {
            const int r0 = warp * 32 + (lane >> 2);
            const int cb = (lane & 3) * 2;
#pragma unroll
            for (int mt = 0; mt < 2; ++mt)
#pragma unroll
                for (int nt = 0; nt < 8; ++nt) {
                    const int c = 8 * nt + cb;
                    const float b0 = sCB2[c], b1 = sCB2[c + 1];
                    const float* a = acc[mt * 8 + nt];
                    float v0 = fmaxf(a[0] + b0, 0.f), v1 = fmaxf(a[1] + b1, 0.f);
                    float v2 = fmaxf(a[2] + b0, 0.f), v3 = fmaxf(a[3] + b1, 0.f);
                    const int rA = r0 + 16 * mt, rB = rA + 8;
                    const int half = (nt < 4) ? SM_AH : SM_AL;
                    const int cc = (nt < 4) ? c : c - 32;
                    *(float2*)(smc + half + rA * ROWB + cc * 4) = make_float2(v0, v1);
                    *(float2*)(smc + half + rB * ROWB + cc * 4) = make_float2(v2, v3);
                }
        }
        __syncwarp();
        // ---- final 64->3 + sigmoid (exact fp32), stage 19-float row ----
        {
            const float* rH = (const float*)(smc + SM_AH + tid * ROWB);
            const float* rL = (const float*)(smc + SM_AL + tid * ROWB);
            float a0 = sCB3[0], a1 = sCB3[1], a2 = sCB3[2];
#pragma unroll 8
            for (int k = 0; k < 32; ++k) {
                const float x = rH[k];
                a0 = fmaf(x, sCW3[3*k + 0], a0);
                a1 = fmaf(x, sCW3[3*k + 1], a1);
                a2 = fmaf(x, sCW3[3*k + 2], a2);
            }
#pragma unroll 8
            for (int k = 0; k < 32; ++k) {
                const float x = rL[k];
                a0 = fmaf(x, sCW3[3*(32+k) + 0], a0);
                a1 = fmaf(x, sCW3[3*(32+k) + 1], a1);
                a2 = fmaf(x, sCW3[3*(32+k) + 2], a2);
            }
            __syncwarp();
            float* orow = (float*)(smc + SM_AH + tid * ROWB);
            orow[0] = 1.0f / (1.0f + expf(-a0));
            orow[1] = 1.0f / (1.0f + expf(-a1));
            orow[2] = 1.0f / (1.0f + expf(-a2));
            orow[3] = fmaxf(df[0], 0.0f);
#pragma unroll
            for (int j = 0; j < 15; ++j) orow[4 + j] = df[1 + j];
        }
        __syncwarp();
        // ---- coalesced per-warp store (32 rows x 19 floats) ----
        {
            const int m = min(TS, n - i0);            // valid samples in tile
            const int vw = min(32, m - warp * 32);    // valid rows this warp
            if (vw > 0) {
                float* gbase = out + (size_t)(i0 + warp * 32) * 19;
                const char* sbase = smc + SM_AH + (warp * 32) * ROWB;
                int s = lane / 19, c = lane % 19;
#pragma unroll
                for (int it = 0; it < 19; ++it) {
                    if (s < vw)
                        gbase[it * 32 + lane] = *(const float*)(sbase + s * ROWB + c * 4);
                    c += 13; s += 1;
                    if (c >= 19) { c -= 19; s += 1; }
                }
            }
        }
        __syncwarp();
    }
}

extern "C" void kernel_launch(void* const* d_in, const int* in_sizes, int n_in,
                              void* d_out, int out_size) {
    const float* rs   = (const float*)d_in[0];
    const float* dirs = (const float*)d_in[1];
    const int*   cam  = (const int*)d_in[2];
    const float* aabb = (const float*)d_in[3];
    const float* ht   = (const float*)d_in[4];
    const float* rw1  = (const float*)d_in[5];
    const float* rb1  = (const float*)d_in[6];
    const float* rw2  = (const float*)d_in[7];
    const float* rb2  = (const float*)d_in[8];
    const float* dw1  = (const float*)d_in[9];
    const float* db1  = (const float*)d_in[10];
    const float* dw2  = (const float*)d_in[11];
    const float* db2  = (const float*)d_in[12];
    const float* dw3  = (const float*)d_in[13];
    const float* db3  = (const float*)d_in[14];
    const float* cw1  = (const float*)d_in[15];
    const float* cb1  = (const float*)d_in[16];
    const float* cw2  = (const float*)d_in[17];
    const float* cb2  = (const float*)d_in[18];
    const float* cw3  = (const float*)d_in[19];
    const float* cb3  = (const float*)d_in[20];
    const float* app  = (const float*)d_in[21];
    float* out = (float*)d_out;

    const int n = in_sizes[0] / 3;

    ResArr ra;
    double growth = exp((log(2048.0) - log(16.0)) / 15.0);
    for (int i = 0; i < 16; ++i)
        ra.r[i] = (int)(16.0 * pow(growth, (double)i));

    cudaFuncSetAttribute(nerf_h2_kernel,
                         cudaFuncAttributeMaxDynamicSharedMemorySize, SMEM_BYTES);

    dim3 grid(148), block(NT);   // 1 CTA/SM persistent, warp-independent tiles
    nerf_h2_kernel<<<grid, block, SMEM_BYTES>>>(
        rs, dirs, cam, aabb, ht,
        rw1, rb1, rw2, rb2,
        dw1, db1, dw2, db2, dw3, db3,
        cw1, cb1, cw2, cb2, cw3, cb3,
        app, out, n, ra);
}